// round 17
// baseline (speedup 1.0000x reference)
#include <cuda_runtime.h>
#include <cstdint>

#define B_   512
#define L_   1024
#define K_   8
#define NR_  512
#define S_   20
#define EXT_ 26
#define SQN  4             // squarings (scale 2^-4); measured rel_err 2.25e-6
#define ROWW (K_ * EXT_)   // 208
#define MSZ  (S_ * S_)     // 400
#define LT   256           // writer strip (validated)
#define NZQ  44            // non-pad quads per row
#define WTH  (8 * NZQ)     // 352 writer threads: 8 positions x 44 lanes
#define CWSEG 512          // positions per const-writer block

// Scratch (device globals; no allocation allowed)
__device__ __align__(16) float g_Q[K_ * MSZ];
__device__ __align__(16) float g_P[(size_t)NR_ * K_ * MSZ];

// quad lanes (of 52) whose 4 elements are all pad (e>=20) for c<20 rows
__constant__ int c_zq[8] = {5, 12, 18, 25, 31, 38, 44, 51};
// the other 44 lanes
__constant__ int c_qmap[NZQ] = {
     0, 1, 2, 3, 4,  6, 7, 8, 9,10,11, 13,14,15,16,17, 19,20,21,22,23,24,
    26,27,28,29,30, 32,33,34,35,36,37, 39,40,41,42,43, 45,46,47,48,49,50
};

__device__ __forceinline__ float softplus_f(float x) {
    return fmaxf(x, 0.0f) + log1pf(expf(-fabsf(x)));
}

// ---------------------------------------------------------------------------
// Kernel A: build Q[k]
// ---------------------------------------------------------------------------
__global__ void qprep_kernel(const float* __restrict__ exch,
                             const float* __restrict__ freq) {
    const int k = blockIdx.x;
    const int i = threadIdx.y;
    const int j = threadIdx.x;

    __shared__ float Rs[S_][S_ + 1];
    __shared__ float diag[S_];
    __shared__ float fr[S_];

    if (i == 0) fr[j] = freq[j];

    float e1 = exch[(k * S_ + i) * S_ + j];
    float e2 = exch[(k * S_ + j) * S_ + i];
    float r = softplus_f(0.5f * (e1 + e2));
    if (i == j) r = 0.0f;
    __syncthreads();

    float q = r * fr[j];
    Rs[i][j] = q;
    __syncthreads();

    if (j == 0) {
        float d = 0.0f;
        #pragma unroll
        for (int t = 0; t < S_; t++) d += Rs[i][t];
        diag[i] = d;
    }
    __syncthreads();

    float mue = 0.0f;
    #pragma unroll
    for (int t = 0; t < S_; t++) mue += fr[t] * diag[t];
    mue = fmaxf(mue, 1e-16f);

    float val = q - (i == j ? diag[i] : 0.0f);
    g_Q[(k * S_ + i) * S_ + j] = val / mue;
}

// ---------------------------------------------------------------------------
// tile helpers
// ---------------------------------------------------------------------------
__device__ __forceinline__ void mm_tile(const float* __restrict__ Lcm,
                                        const float* __restrict__ Rrm,
                                        int a, int bb, float acc[4][4]) {
    #pragma unroll
    for (int r = 0; r < 4; r++)
        #pragma unroll
        for (int c = 0; c < 4; c++) acc[r][c] = 0.0f;
    #pragma unroll
    for (int t = 0; t < S_; t++) {
        const float4 lv = *(const float4*)(Lcm + t * S_ + 4 * a);
        const float4 rv = *(const float4*)(Rrm + t * S_ + 4 * bb);
        const float* lp = &lv.x;
        const float* rp = &rv.x;
        #pragma unroll
        for (int r = 0; r < 4; r++)
            #pragma unroll
            for (int c = 0; c < 4; c++)
                acc[r][c] = fmaf(lp[r], rp[c], acc[r][c]);
    }
}
__device__ __forceinline__ void wr_rm(float* B, const float t[4][4], int a, int bb) {
    #pragma unroll
    for (int r = 0; r < 4; r++) {
        float4 v = make_float4(t[r][0], t[r][1], t[r][2], t[r][3]);
        *(float4*)(B + (4 * a + r) * S_ + 4 * bb) = v;
    }
}
__device__ __forceinline__ void wr_cm(float* B, const float t[4][4], int a, int bb) {
    #pragma unroll
    for (int c = 0; c < 4; c++) {
        float4 v = make_float4(t[0][c], t[1][c], t[2][c], t[3][c]);
        *(float4*)(B + (4 * bb + c) * S_ + 4 * a) = v;
    }
}

// ---------------------------------------------------------------------------
// expm (PRIMARY — proven config: 256 thr, 8 warps = 8 matrices (one r),
// 2 static smem buffers/warp). PS degree-8 + 4 squarings (8 matmuls),
// scale 2^-4. Inline used-check. Signals launch_dependents at entry.
// ---------------------------------------------------------------------------
__global__ void __launch_bounds__(256)
expm_ps_kernel(const float* __restrict__ tau_kernel,
               const int* __restrict__ rate_indices) {
    asm volatile("griddepcontrol.launch_dependents;" ::: "memory");

    const int lane = threadIdx.x & 31;
    const int w    = threadIdx.x >> 5;
    const int r    = blockIdx.x;
    const int k    = w;

    int f = 0;
    #pragma unroll
    for (int t = threadIdx.x; t < B_; t += 256)
        f |= (__ldg(rate_indices + t) == r);
    if (!__syncthreads_or(f)) return;

    __shared__ __align__(16) float sb[8][2][MSZ];   // 25.6 KB
    float* B0 = sb[w][0];
    float* B1 = sb[w][1];

    const bool act = (lane < 25);
    const int  a   = lane / 5;
    const int  bb  = lane - a * 5;

    const float scale = softplus_f(__ldg(tau_kernel + r)) * (1.0f / 16.0f);

    float at[4][4], A2t[4][4], acc[4][4], P[4][4];

    if (act) {
        #pragma unroll
        for (int r4 = 0; r4 < 4; r4++) {
            float4 q = *(const float4*)(g_Q + (k * S_ + 4 * a + r4) * S_ + 4 * bb);
            at[r4][0] = q.x * scale; at[r4][1] = q.y * scale;
            at[r4][2] = q.z * scale; at[r4][3] = q.w * scale;
        }
        wr_rm(B0, at, a, bb);
        wr_cm(B1, at, a, bb);
    }
    __syncwarp();
    if (act) mm_tile(B1, B0, a, bb, A2t);        // A2 = A*A
    __syncwarp();
    if (act) wr_cm(B1, A2t, a, bb);
    __syncwarp();
    if (act) mm_tile(B1, B0, a, bb, acc);        // A3 = A2*A
    __syncwarp();
    if (act) {
        wr_cm(B1, acc, a, bb);                   // B1 = A3 cm
        float q[4][4];                           // q2
        #pragma unroll
        for (int r4 = 0; r4 < 4; r4++)
            #pragma unroll
            for (int c = 0; c < 4; c++)
                q[r4][c] = ((4 * a + r4) == (4 * bb + c) ? (1.0f / 720.0f) : 0.0f)
                         + at[r4][c] * (1.0f / 5040.0f)
                         + A2t[r4][c] * (1.0f / 40320.0f);
        wr_rm(B0, q, a, bb);
    }
    __syncwarp();
    if (act) mm_tile(B1, B0, a, bb, acc);        // M = A3*q2
    __syncwarp();
    if (act) {
        float q[4][4];                           // N = q1 + M
        #pragma unroll
        for (int r4 = 0; r4 < 4; r4++)
            #pragma unroll
            for (int c = 0; c < 4; c++)
                q[r4][c] = ((4 * a + r4) == (4 * bb + c) ? (1.0f / 6.0f) : 0.0f)
                         + at[r4][c] * (1.0f / 24.0f)
                         + A2t[r4][c] * (1.0f / 120.0f)
                         + acc[r4][c];
        wr_rm(B0, q, a, bb);
    }
    __syncwarp();
    if (act) {
        mm_tile(B1, B0, a, bb, acc);             // A3*N
        #pragma unroll
        for (int r4 = 0; r4 < 4; r4++)           // P = I + A + A2/2 + A3*N
            #pragma unroll
            for (int c = 0; c < 4; c++)
                P[r4][c] = ((4 * a + r4) == (4 * bb + c) ? 1.0f : 0.0f)
                         + at[r4][c]
                         + A2t[r4][c] * 0.5f
                         + acc[r4][c];
    }

    #pragma unroll 1
    for (int q = 0; q < SQN; q++) {
        __syncwarp();
        if (act) { wr_rm(B0, P, a, bb); wr_cm(B1, P, a, bb); }
        __syncwarp();
        if (act) {
            mm_tile(B1, B0, a, bb, acc);
            #pragma unroll
            for (int r4 = 0; r4 < 4; r4++)
                #pragma unroll
                for (int c = 0; c < 4; c++) P[r4][c] = acc[r4][c];
        }
    }

    if (act) {
        float* dst = g_P + (size_t)(r * K_ + k) * MSZ;
        #pragma unroll
        for (int r4 = 0; r4 < 4; r4++) {
            float4 v = make_float4(P[r4][0], P[r4][1], P[r4][2], P[r4][3]);
            *(float4*)(dst + (4 * a + r4) * S_ + 4 * bb) = v;
        }
    }
}

// ---------------------------------------------------------------------------
// Const writer (SECONDARY via PDL; reads nothing from expm, no wait).
// Stores ALL expm-independent output: one-hot rows (c>=20, full 52 quads)
// AND pad-zero ZQ quads for c<20 rows. Two compacted lists -> dense loops.
// ---------------------------------------------------------------------------
__global__ void __launch_bounds__(256)
constwr_kernel(const int* __restrict__ inputs, float* __restrict__ out) {
    const int tid  = threadIdx.x;
    const int b    = blockIdx.y;
    const int base = blockIdx.x * CWSEG;

    __shared__ int cntA, cntB;
    __shared__ int listA[CWSEG];   // positions with c>=20 (packed with c)
    __shared__ int listB[CWSEG];   // positions with c<20

    if (tid == 0) { cntA = 0; cntB = 0; }
    __syncthreads();

    const int* crow = inputs + (size_t)b * L_ + base;
    #pragma unroll
    for (int t = tid; t < CWSEG; t += 256) {
        const int c = __ldg(crow + t);
        if (c >= S_) {
            int s = atomicAdd(&cntA, 1);
            listA[s] = (t << 5) | c;
        } else {
            int s = atomicAdd(&cntB, 1);
            listB[s] = t;
        }
    }
    __syncthreads();

    float4* ob = (float4*)out + ((size_t)b * L_ + base) * 52;

    // dense one-hot stores: 208 threads = 4 positions x 52 lanes
    const int nA = cntA;
    if (tid < 208) {
        const int j  = tid % 52;
        const int i0 = tid / 52;
        int e[4];
        #pragma unroll
        for (int u = 0; u < 4; u++) {
            int f = 4 * j + u;
            int kx = f / EXT_;
            e[u] = f - kx * EXT_;
        }
        #pragma unroll 2
        for (int ii = i0; ii < nA; ii += 4) {
            const int pc = listA[ii];
            const int p  = pc >> 5;
            const int c  = pc & 31;
            float4 v;
            v.x = (e[0] == c) ? 1.0f : 0.0f;
            v.y = (e[1] == c) ? 1.0f : 0.0f;
            v.z = (e[2] == c) ? 1.0f : 0.0f;
            v.w = (e[3] == c) ? 1.0f : 0.0f;
            __stcs(ob + (size_t)p * 52 + j, v);
        }
    }

    // dense zero stores at ZQ lanes: 256 threads = 32 positions x 8 lanes
    const int nB = cntB;
    {
        const int zj  = c_zq[tid & 7];
        const int pi0 = tid >> 3;            // 0..31
        const float4 z4 = make_float4(0.f, 0.f, 0.f, 0.f);
        #pragma unroll 2
        for (int ii = pi0; ii < nB; ii += 32) {
            const int p = listB[ii];
            __stcs(ob + (size_t)p * 52 + zj, z4);
        }
    }
}

// ---------------------------------------------------------------------------
// Main writer: c<20 positions, only the 44 non-pad quads per row.
// 352 threads = 8 positions x 44 lanes. RT = 20 expm rows.
// ---------------------------------------------------------------------------
__global__ void __launch_bounds__(WTH)
writer_kernel(const int* __restrict__ inputs,
              const int* __restrict__ rate_indices,
              float* __restrict__ out) {
    const int b   = blockIdx.y;
    const int l0  = blockIdx.x * LT;
    const int tid = threadIdx.x;

    __shared__ __align__(16) float RT[S_ * ROWW];   // 16.6 KB
    __shared__ int cs[LT];

    for (int t = tid; t < LT; t += WTH)
        cs[t] = inputs[b * L_ + l0 + t];

    const int r = rate_indices[b];
    const float* Pr = g_P + (size_t)(r * K_) * MSZ;
    for (int idx = tid; idx < S_ * ROWW; idx += WTH) {
        const int c = idx / ROWW;
        const int f = idx - c * ROWW;
        const int kk = f / EXT_;
        const int e  = f - kk * EXT_;
        RT[idx] = (e < S_) ? Pr[kk * MSZ + c * S_ + e] : 0.0f;
    }
    __syncthreads();

    const int j  = c_qmap[tid % NZQ];               // non-pad quad lane
    const int p0 = tid / NZQ;                       // 0..7
    const float4* RT4 = (const float4*)RT;
    float4* ob = (float4*)out + ((size_t)b * L_ + l0) * 52;

    #pragma unroll 4
    for (int p = p0; p < LT; p += 8) {
        const int c = cs[p];
        if (c < S_)
            __stcs(ob + (size_t)p * 52 + j, RT4[c * 52 + j]);
    }
}

// ---------------------------------------------------------------------------
extern "C" void kernel_launch(void* const* d_in, const int* in_sizes, int n_in,
                              void* d_out, int out_size) {
    const int*   inputs       = (const int*)  d_in[0];
    const int*   rate_indices = (const int*)  d_in[1];
    const float* tau_kernel   = (const float*)d_in[2];
    const float* exch         = (const float*)d_in[3];
    const float* freq         = (const float*)d_in[4];
    float*       out          = (float*)d_out;

    (void)in_sizes; (void)n_in; (void)out_size;

    dim3 tb(S_, S_);
    qprep_kernel<<<K_, tb>>>(exch, freq);

    // PRIMARY: expm, signals dependents at entry
    expm_ps_kernel<<<NR_, 256>>>(tau_kernel, rate_indices);

    // SECONDARY: all expm-independent stores co-run under expm (PDL, no wait)
    cudaLaunchConfig_t cfg = {};
    cfg.gridDim  = dim3(L_ / CWSEG, B_, 1);
    cfg.blockDim = dim3(256, 1, 1);
    cfg.dynamicSmemBytes = 0;
    cfg.stream = 0;
    cudaLaunchAttribute attrs[1];
    attrs[0].id = cudaLaunchAttributeProgrammaticStreamSerialization;
    attrs[0].val.programmaticStreamSerializationAllowed = 1;
    cfg.attrs = attrs;
    cfg.numAttrs = 1;
    cudaError_t st = cudaLaunchKernelEx(&cfg, constwr_kernel, inputs, out);
    if (st != cudaSuccess) {
        dim3 ogrid(L_ / CWSEG, B_);
        constwr_kernel<<<ogrid, 256>>>(inputs, out);
    }

    // Main writer (full barrier behind both)
    dim3 grid(L_ / LT, B_);
    writer_kernel<<<grid, WTH>>>(inputs, rate_indices, out);
}